// round 1
// baseline (speedup 1.0000x reference)
#include <cuda_runtime.h>

// Reference semantics (after dead-code elimination):
//   r  = eye(3)
//   tb = -mean(mkpts0, axis=1)   // mkpts0 is [3, N] row-major
// Output: r (9 floats, row-major) followed by tb (3 floats) = 12 floats.
// mkpts1 and valid_scores are unused by the output.

#define NTHREADS 1024

__global__ void svdhead_kernel(const float* __restrict__ mkpts0,
                               int n, float* __restrict__ out, int out_size) {
    __shared__ float red[3][32];  // per-warp partials for each of the 3 rows

    int tid  = threadIdx.x;
    int lane = tid & 31;
    int warp = tid >> 5;

    float s0 = 0.f, s1 = 0.f, s2 = 0.f;
    const float* r0 = mkpts0;
    const float* r1 = mkpts0 + n;
    const float* r2 = mkpts0 + 2 * n;
    for (int j = tid; j < n; j += NTHREADS) {
        s0 += r0[j];
        s1 += r1[j];
        s2 += r2[j];
    }

    // warp reduce
    #pragma unroll
    for (int off = 16; off > 0; off >>= 1) {
        s0 += __shfl_down_sync(0xFFFFFFFFu, s0, off);
        s1 += __shfl_down_sync(0xFFFFFFFFu, s1, off);
        s2 += __shfl_down_sync(0xFFFFFFFFu, s2, off);
    }
    if (lane == 0) {
        red[0][warp] = s0;
        red[1][warp] = s1;
        red[2][warp] = s2;
    }
    __syncthreads();

    if (warp == 0) {
        int nwarps = NTHREADS / 32;
        float t0 = (lane < nwarps) ? red[0][lane] : 0.f;
        float t1 = (lane < nwarps) ? red[1][lane] : 0.f;
        float t2 = (lane < nwarps) ? red[2][lane] : 0.f;
        #pragma unroll
        for (int off = 16; off > 0; off >>= 1) {
            t0 += __shfl_down_sync(0xFFFFFFFFu, t0, off);
            t1 += __shfl_down_sync(0xFFFFFFFFu, t1, off);
            t2 += __shfl_down_sync(0xFFFFFFFFu, t2, off);
        }
        if (lane == 0) {
            float inv_n = 1.0f / (float)n;
            // r = identity (row-major)
            if (out_size >= 9) {
                out[0] = 1.f; out[1] = 0.f; out[2] = 0.f;
                out[3] = 0.f; out[4] = 1.f; out[5] = 0.f;
                out[6] = 0.f; out[7] = 0.f; out[8] = 1.f;
            }
            // tb = -r @ src_mean = -mean
            if (out_size >= 12) {
                out[9]  = -t0 * inv_n;
                out[10] = -t1 * inv_n;
                out[11] = -t2 * inv_n;
            }
            // Defensive: fill any extra poisoned tail with zeros
            for (int i = 12; i < out_size; i++) out[i] = 0.f;
        }
    }
}

extern "C" void kernel_launch(void* const* d_in, const int* in_sizes, int n_in,
                              void* d_out, int out_size) {
    const float* mkpts0 = (const float*)d_in[0];
    int n = in_sizes[0] / 3;  // mkpts0 is [3, N]
    float* out = (float*)d_out;
    svdhead_kernel<<<1, NTHREADS>>>(mkpts0, n, out, out_size);
}